// round 1
// baseline (speedup 1.0000x reference)
#include <cuda_runtime.h>
#include <cstdint>

// Problem constants
#define ROWG   64
#define IN_DIM 1024
#define OUT_D  1024
#define BATCH  512

// Tiling
#define BM 128
#define BN 128
#define BK 16
#define ASTRIDE (BK + 4)    // 20 floats -> conflict-free A frag loads
#define BSTRIDE (BN + 8)    // 136 floats -> conflict-free B frag loads
#define KTILES (IN_DIM / BK) // 64

__device__ __forceinline__ uint32_t f2tf(float v) {
    uint32_t t;
    asm("cvt.rna.tf32.f32 %0, %1;" : "=r"(t) : "f"(v));
    return t;
}

__device__ __forceinline__ void mma_tf32(float* c, const uint32_t* a, const uint32_t* b) {
    asm volatile(
        "mma.sync.aligned.m16n8k8.row.col.f32.tf32.tf32.f32 "
        "{%0,%1,%2,%3}, {%4,%5,%6,%7}, {%8,%9}, {%0,%1,%2,%3};\n"
        : "+f"(c[0]), "+f"(c[1]), "+f"(c[2]), "+f"(c[3])
        : "r"(a[0]), "r"(a[1]), "r"(a[2]), "r"(a[3]),
          "r"(b[0]), "r"(b[1]));
}

__device__ __forceinline__ void cp_async16(void* smem_dst, const void* gmem_src) {
    uint32_t dst = (uint32_t)__cvta_generic_to_shared(smem_dst);
    asm volatile("cp.async.cg.shared.global [%0], [%1], 16;\n" :: "r"(dst), "l"(gmem_src));
}

__global__ __launch_bounds__(256, 2)
void group_mlp_tf32_kernel(const float* __restrict__ x,
                           const float* __restrict__ W,
                           const float* __restrict__ bias,
                           float* __restrict__ out)
{
    __shared__ float As[2][BM][ASTRIDE];  // 2*128*20*4  = 20480 B
    __shared__ float Bs[2][BK][BSTRIDE];  // 2*16*136*4  = 17408 B

    const int r  = blockIdx.z;            // group row 0..63
    const int n0 = blockIdx.x * BN;       // output-col tile
    const int m0 = blockIdx.y * BM;       // batch tile

    const int tid  = threadIdx.x;
    const int warp = tid >> 5;
    const int lane = tid & 31;
    const int wm   = warp & 3;            // warp row 0..3 (32 rows each)
    const int wn   = warp >> 2;           // warp col 0..1 (64 cols each)
    const int g    = lane >> 2;           // groupID 0..7
    const int tg   = lane & 3;            // thread-in-group 0..3

    // x[b, r, i] at (b*ROWG + r)*IN_DIM + i
    const float* xg = x + (size_t)r * IN_DIM;
    const float* Wg = W + (size_t)r * IN_DIM * OUT_D;

    float acc[2][8][4];
    #pragma unroll
    for (int mt = 0; mt < 2; mt++)
        #pragma unroll
        for (int nt = 0; nt < 8; nt++)
            #pragma unroll
            for (int i = 0; i < 4; i++)
                acc[mt][nt][i] = 0.0f;

    // ---- tile loader (cp.async, 16B) ----
    // A tile: 128 rows x 16 floats = 512 float4 chunks, 2 per thread
    // B tile: 16 rows x 128 floats = 512 float4 chunks, 2 per thread
    auto load_tile = [&](int kt, int buf) {
        const int k0 = kt * BK;
        #pragma unroll
        for (int i = 0; i < 2; i++) {
            int c = tid + i * 256;
            int arow = c >> 2;
            int acol = (c & 3) * 4;
            const float* src = xg + (size_t)(m0 + arow) * (ROWG * IN_DIM) + k0 + acol;
            cp_async16(&As[buf][arow][acol], src);
        }
        #pragma unroll
        for (int i = 0; i < 2; i++) {
            int c = tid + i * 256;
            int brow = c >> 5;
            int bcol = (c & 31) * 4;
            const float* src = Wg + (size_t)(k0 + brow) * OUT_D + n0 + bcol;
            cp_async16(&Bs[buf][brow][bcol], src);
        }
        asm volatile("cp.async.commit_group;\n");
    };

    load_tile(0, 0);

    for (int kt = 0; kt < KTILES; kt++) {
        const int buf = kt & 1;
        if (kt + 1 < KTILES) {
            load_tile(kt + 1, (kt + 1) & 1);
            asm volatile("cp.async.wait_group 1;\n");
        } else {
            asm volatile("cp.async.wait_group 0;\n");
        }
        __syncthreads();

        #pragma unroll
        for (int ks = 0; ks < 2; ks++) {
            const int kk = ks * 8;
            uint32_t af[2][4];
            uint32_t bf[8][2];

            #pragma unroll
            for (int mt = 0; mt < 2; mt++) {
                int row = wm * 32 + mt * 16 + g;
                af[mt][0] = f2tf(As[buf][row    ][kk + tg    ]);
                af[mt][1] = f2tf(As[buf][row + 8][kk + tg    ]);
                af[mt][2] = f2tf(As[buf][row    ][kk + tg + 4]);
                af[mt][3] = f2tf(As[buf][row + 8][kk + tg + 4]);
            }
            #pragma unroll
            for (int nt = 0; nt < 8; nt++) {
                int col = wn * 64 + nt * 8 + g;
                bf[nt][0] = f2tf(Bs[buf][kk + tg    ][col]);
                bf[nt][1] = f2tf(Bs[buf][kk + tg + 4][col]);
            }
            #pragma unroll
            for (int mt = 0; mt < 2; mt++)
                #pragma unroll
                for (int nt = 0; nt < 8; nt++)
                    mma_tf32(acc[mt][nt], af[mt], bf[nt]);
        }
        __syncthreads();
    }

    // ---- epilogue: add bias, store (out layout == x layout) ----
    const float* bp = bias + (size_t)r * OUT_D + n0;
    #pragma unroll
    for (int mt = 0; mt < 2; mt++) {
        #pragma unroll
        for (int nt = 0; nt < 8; nt++) {
            int row0 = wm * 32 + mt * 16 + g;
            int col  = wn * 64 + nt * 8 + tg * 2;
            float b0 = bp[col];
            float b1 = bp[col + 1];
            float2 v0 = make_float2(acc[mt][nt][0] + b0, acc[mt][nt][1] + b1);
            float2 v1 = make_float2(acc[mt][nt][2] + b0, acc[mt][nt][3] + b1);
            size_t o0 = ((size_t)(m0 + row0)     * ROWG + r) * OUT_D + n0 + col;
            size_t o1 = ((size_t)(m0 + row0 + 8) * ROWG + r) * OUT_D + n0 + col;
            *reinterpret_cast<float2*>(out + o0) = v0;
            *reinterpret_cast<float2*>(out + o1) = v1;
        }
    }
}

extern "C" void kernel_launch(void* const* d_in, const int* in_sizes, int n_in,
                              void* d_out, int out_size) {
    const float* x    = (const float*)d_in[0];  // (512, 64, 1024)
    const float* W    = (const float*)d_in[1];  // (64, 1024, 1024)
    const float* bias = (const float*)d_in[2];  // (64, 1024)
    float* out = (float*)d_out;                 // (512, 64, 1024)

    dim3 grid(OUT_D / BN, BATCH / BM, ROWG);    // (8, 4, 64)
    dim3 block(256);
    group_mlp_tf32_kernel<<<grid, block>>>(x, W, bias, out);
}